// round 7
// baseline (speedup 1.0000x reference)
#include <cuda_runtime.h>
#include <cstdint>

// Problem constants
#define TT   512      // sequence length
#define EE   1024     // embedding dim
#define HDIM 512      // per-direction hidden
#define G4   2048     // 4*HDIM gate rows
#define KTAG 32       // tags
#define NEGV (-10000.0f)
#define START_TAG 30
#define STOP_TAG  31

// LSTM recurrent kernel config
#define NBD  64              // blocks per direction
#define JPB  (HDIM / NBD)    // h-indices per block = 8
#define LSTM_THREADS 256
#define SENT 0x7FC00001u     // NaN sentinel: h = sigmoid*tanh can never be NaN

// ---------------- scratch (device globals; no allocation) ----------------
__device__ float g_xw[2][TT][G4];          // input projections + biases (scan-step indexed)
__device__ float g_lstm[TT][2 * HDIM];     // concatenated [hf | hb] (time indexed)
__device__ float g_feats[TT][KTAG];        // tag scores
__device__ float g_hx[2][TT][NBD][JPB];    // per-step h exchange slots (2 MB)

// ---------------- asm helpers ----------------
__device__ __forceinline__ float4 ldg_relaxed_v4(const float4* p) {
    float4 v;
    asm volatile("ld.global.relaxed.gpu.v4.f32 {%0,%1,%2,%3}, [%4];"
                 : "=f"(v.x), "=f"(v.y), "=f"(v.z), "=f"(v.w) : "l"(p) : "memory");
    return v;
}
__device__ __forceinline__ void stg_relaxed_f32(float* p, float v) {
    asm volatile("st.global.relaxed.gpu.f32 [%0], %1;" :: "l"(p), "f"(v) : "memory");
}
__device__ __forceinline__ bool has_sent(float4 v) {
    return (__float_as_uint(v.x) == SENT) | (__float_as_uint(v.y) == SENT) |
           (__float_as_uint(v.z) == SENT) | (__float_as_uint(v.w) == SENT);
}
// packed f32x2 FMA (sm_100+; ptxas never emits this from C++)
__device__ __forceinline__ void fma2(uint64_t& d, uint64_t a, uint64_t b) {
    asm("fma.rn.f32x2 %0, %1, %2, %0;" : "+l"(d) : "l"(a), "l"(b));
}
__device__ __forceinline__ uint64_t pack2(float x, float y) {
    uint64_t r; asm("mov.b64 %0, {%1,%2};" : "=l"(r) : "f"(x), "f"(y)); return r;
}
__device__ __forceinline__ float2 unpack2(uint64_t v) {
    float2 f; asm("mov.b64 {%0,%1}, %2;" : "=f"(f.x), "=f"(f.y) : "l"(v)); return f;
}
__device__ __forceinline__ void lds_v2_u64(uint32_t addr, uint64_t& x, uint64_t& y) {
    asm volatile("ld.shared.v2.b64 {%0,%1}, [%2];" : "=l"(x), "=l"(y) : "r"(addr));
}
// fast activations: MUFU-based, rel err ~1e-6 (safe vs argmax margins)
__device__ __forceinline__ float fast_sig(float x) {
    return __fdividef(1.f, 1.f + __expf(-x));
}
__device__ __forceinline__ float fast_tanh(float x) {
    return 1.f - __fdividef(2.f, __expf(2.f * x) + 1.f);
}

// ---------------- poison the exchange slots each launch ----------------
__global__ __launch_bounds__(256) void poison_kernel() {
    // g_hx = 2*512*64*8 floats = 131072 float4
    float4* p = (float4*)g_hx;
    uint32_t s = SENT;
    float4 v = make_float4(__uint_as_float(s), __uint_as_float(s),
                           __uint_as_float(s), __uint_as_float(s));
    p[blockIdx.x * 256 + threadIdx.x] = v;
}

// ---------------- Kernel A: embed-gather + input projection GEMM ---------
// 128x128 tile, 8x8 per thread, packed f32x2 FMA inner loop.
__global__ __launch_bounds__(256, 1) void gemm_xw_kernel(
    const int* __restrict__ sentence,
    const float* __restrict__ embed,
    const float* __restrict__ w_ih_f, const float* __restrict__ b_ih_f,
    const float* __restrict__ b_hh_f,
    const float* __restrict__ w_ih_b, const float* __restrict__ b_ih_b,
    const float* __restrict__ b_hh_b)
{
    int dir = blockIdx.z;
    const float* W  = dir ? w_ih_b : w_ih_f;
    const float* Bi = dir ? b_ih_b : b_ih_f;
    const float* Bh = dir ? b_hh_b : b_hh_f;

    int n0 = blockIdx.x * 128;   // gate-row tile
    int m0 = blockIdx.y * 128;   // scan-step tile

    __shared__ __align__(16) float As[8][128];
    __shared__ __align__(16) float Bs[8][128];

    int tid = threadIdx.x;
    int tx = tid & 15;           // 0..15 -> 8 output cols
    int ty = tid >> 4;           // 0..15 -> 8 output rows

    int lrow = tid >> 1;         // 0..127 load row
    int lq   = tid & 1;          // which float4 of the 8-wide k slab

    int sglob = m0 + lrow;                       // scan step
    int sidx  = dir ? (TT - 1 - sglob) : sglob;  // token consumed there
    const float* aptr = embed + (size_t)sentence[sidx] * EE + lq * 4;
    const float* bptr = W + (size_t)(n0 + lrow) * EE + lq * 4;

    uint64_t acc2[8][4];
#pragma unroll
    for (int i = 0; i < 8; i++)
#pragma unroll
        for (int j = 0; j < 4; j++) acc2[i][j] = 0ull;

    uint32_t bs_base = (uint32_t)__cvta_generic_to_shared(&Bs[0][tx * 8]);
    uint32_t as_base = (uint32_t)__cvta_generic_to_shared(&As[0][ty * 8]);

    float4 a_nx = *(const float4*)aptr;
    float4 b_nx = *(const float4*)bptr;

    for (int k0 = 0; k0 < EE; k0 += 8) {
        As[lq * 4 + 0][lrow] = a_nx.x; As[lq * 4 + 1][lrow] = a_nx.y;
        As[lq * 4 + 2][lrow] = a_nx.z; As[lq * 4 + 3][lrow] = a_nx.w;
        Bs[lq * 4 + 0][lrow] = b_nx.x; Bs[lq * 4 + 1][lrow] = b_nx.y;
        Bs[lq * 4 + 2][lrow] = b_nx.z; Bs[lq * 4 + 3][lrow] = b_nx.w;
        __syncthreads();

        if (k0 + 8 < EE) {
            a_nx = *(const float4*)(aptr + k0 + 8);
            b_nx = *(const float4*)(bptr + k0 + 8);
        }

#pragma unroll
        for (int k = 0; k < 8; k++) {
            uint64_t a01, a23, a45, a67;
            lds_v2_u64(as_base + k * 512,      a01, a23);
            lds_v2_u64(as_base + k * 512 + 16, a45, a67);
            uint64_t b01, b23, b45, b67;
            lds_v2_u64(bs_base + k * 512,      b01, b23);
            lds_v2_u64(bs_base + k * 512 + 16, b45, b67);
            float2 a0 = unpack2(a01), a1 = unpack2(a23);
            float2 a2 = unpack2(a45), a3 = unpack2(a67);
            float a[8] = {a0.x, a0.y, a1.x, a1.y, a2.x, a2.y, a3.x, a3.y};
#pragma unroll
            for (int i = 0; i < 8; i++) {
                uint64_t aa = pack2(a[i], a[i]);
                fma2(acc2[i][0], aa, b01);
                fma2(acc2[i][1], aa, b23);
                fma2(acc2[i][2], aa, b45);
                fma2(acc2[i][3], aa, b67);
            }
        }
        __syncthreads();
    }

    int rbase = n0 + tx * 8;
    float4 bi0 = *(const float4*)(Bi + rbase);
    float4 bi1 = *(const float4*)(Bi + rbase + 4);
    float4 bh0 = *(const float4*)(Bh + rbase);
    float4 bh1 = *(const float4*)(Bh + rbase + 4);
    float bias[8] = {bi0.x + bh0.x, bi0.y + bh0.y, bi0.z + bh0.z, bi0.w + bh0.w,
                     bi1.x + bh1.x, bi1.y + bh1.y, bi1.z + bh1.z, bi1.w + bh1.w};
#pragma unroll
    for (int i = 0; i < 8; i++) {
        int m = m0 + ty * 8 + i;
        float2 p0 = unpack2(acc2[i][0]);
        float2 p1 = unpack2(acc2[i][1]);
        float2 p2 = unpack2(acc2[i][2]);
        float2 p3 = unpack2(acc2[i][3]);
        float4 o0 = make_float4(p0.x + bias[0], p0.y + bias[1],
                                p1.x + bias[2], p1.y + bias[3]);
        float4 o1 = make_float4(p2.x + bias[4], p2.y + bias[5],
                                p3.x + bias[6], p3.y + bias[7]);
        *(float4*)&g_xw[dir][m][rbase]     = o0;
        *(float4*)&g_xw[dir][m][rbase + 4] = o1;
    }
}

// ---------------- Kernel B: persistent recurrent LSTM --------------------
// Warp-per-j: warp w owns hidden index j0+w; lane = gate*8 + k8 dots a
// 64-element segment (rotated, conflict-free). Gates reduce intra-warp,
// activations parallel across warps, lane0 stores the 4B exchange word.
// Data-is-the-flag exchange with 4-slot pipelined polling.
__global__ __launch_bounds__(LSTM_THREADS, 1) void lstm_kernel(
    const float* __restrict__ w_hh_f,
    const float* __restrict__ w_hh_b,
    const float* __restrict__ h0,
    const float* __restrict__ c0)
{
    __shared__ __align__(16) float hbuf[HDIM];

    int bid = blockIdx.x;
    int dir = bid / NBD;
    int blk = bid % NBD;
    int j0  = blk * JPB;
    int tid = threadIdx.x;
    int wid  = tid >> 5;          // warp = owned j offset (0..7)
    int lane = tid & 31;
    int gate = lane >> 3;         // 0..3 = i,f,g,o
    int k8   = lane & 7;          // 64-element segment index

    const float* w_hh = dir ? w_hh_b : w_hh_f;
    int jglob = j0 + wid;

    // Weights: row (gate*HDIM + jglob), segment [k8*64, k8*64+64), rotated.
    const ulonglong2* wrow =
        (const ulonglong2*)(w_hh + (size_t)(gate * HDIM + jglob) * HDIM);
    uint64_t wp[32];
#pragma unroll
    for (int i = 0; i < 16; i++) {
        int F = k8 * 16 + ((i + k8) & 15);
        ulonglong2 wv = wrow[F];
        wp[2 * i]     = wv.x;
        wp[2 * i + 1] = wv.y;
    }

    float c_reg = (lane == 0) ? c0[dir * HDIM + jglob] : 0.f;

    int pw = tid >> 1;            // writer block this thread tracks (tid<128)
    int pq = tid & 1;             // which 16B chunk of that writer's payload
    const float* xwrow = &g_xw[dir][0][gate * HDIM + jglob];
    const ulonglong2* h16 = (const ulonglong2*)hbuf;

    for (int s = 0; s < TT; s++) {
        int t = dir ? (TT - 1 - s) : s;

        // prefetch xw for the 4 gate leaders (overlaps the poll)
        float xwv = 0.f;
        if (k8 == 0) xwv = __ldcg(xwrow + (size_t)s * G4);

        // fetch h into registers (poll overlaps straggler warps' step s-1)
        float4 hv4;
        if (s > 0 && tid < 128) {
            const float4* src = (const float4*)&g_hx[dir][s - 1][pw][0] + pq;
            // 4-slot pipelined poll: sample period ~lat/4 instead of ~lat
            float4 q0 = ldg_relaxed_v4(src);
            float4 q1 = ldg_relaxed_v4(src);
            float4 q2 = ldg_relaxed_v4(src);
            float4 q3 = ldg_relaxed_v4(src);
            for (;;) {
                if (!has_sent(q0)) { hv4 = q0; break; }
                q0 = ldg_relaxed_v4(src);
                if (!has_sent(q1)) { hv4 = q1; break; }
                q1 = ldg_relaxed_v4(src);
                if (!has_sent(q2)) { hv4 = q2; break; }
                q2 = ldg_relaxed_v4(src);
                if (!has_sent(q3)) { hv4 = q3; break; }
                q3 = ldg_relaxed_v4(src);
            }
        }
        __syncthreads();   // bar1: all warps done reading hbuf at step s-1

        if (s == 0) {
            if (tid < 128)
                ((float4*)hbuf)[tid] = ((const float4*)(h0 + dir * HDIM))[tid];
        } else if (tid < 128) {
            ((float4*)hbuf)[tid] = hv4;
        }
        __syncthreads();   // bar2: hbuf ready

        // dot: 64 elements per lane, rotated segment -> conflict-free LDS.128
        uint64_t accA = 0ull, accB = 0ull;
#pragma unroll
        for (int i = 0; i < 16; i++) {
            int F = k8 * 16 + ((i + k8) & 15);
            ulonglong2 hp = h16[F];
            fma2(accA, wp[2 * i],     hp.x);
            fma2(accB, wp[2 * i + 1], hp.y);
        }
        float2 fA = unpack2(accA), fB = unpack2(accB);
        float acc = (fA.x + fA.y) + (fB.x + fB.y);
        acc += __shfl_down_sync(0xffffffffu, acc, 4, 8);
        acc += __shfl_down_sync(0xffffffffu, acc, 2, 8);
        acc += __shfl_down_sync(0xffffffffu, acc, 1, 8);

        // gate leaders (lanes 0,8,16,24) activate in parallel
        float red = acc + xwv;
        float act = (gate == 2) ? fast_tanh(red) : fast_sig(red);
        float fS = __shfl_sync(0xffffffffu, act, 8);
        float gS = __shfl_sync(0xffffffffu, act, 16);
        float oS = __shfl_sync(0xffffffffu, act, 24);
        if (lane == 0) {
            c_reg = fmaf(fS, c_reg, act * gS);    // act = sigmoid(i)
            float hv = oS * fast_tanh(c_reg);
            stg_relaxed_f32(&g_hx[dir][s][blk][wid], hv);   // critical path
            g_lstm[t][dir * HDIM + jglob] = hv;             // for tag kernel
        }
    }
}

// ---------------- Kernel C: tag projection ----------------
__global__ __launch_bounds__(256) void tag_kernel(
    const float* __restrict__ w_tag, const float* __restrict__ b_tag)
{
    int t = blockIdx.x;
    __shared__ __align__(16) float row[2 * HDIM];
    int tid = threadIdx.x; // 256
    ((float4*)row)[tid] = ((const float4*)&g_lstm[t][0])[tid];
    __syncthreads();

    int lane8 = tid & 7;
    int k = tid >> 3;     // 0..31
    const float4* wr = (const float4*)(w_tag + (size_t)k * 2 * HDIM);
    const float4* r4 = (const float4*)row;
    float acc = 0.f;
#pragma unroll
    for (int i = 0; i < 32; i++) {
        float4 w = wr[lane8 + 8 * i];
        float4 x = r4[lane8 + 8 * i];
        acc = fmaf(w.x, x.x, acc);
        acc = fmaf(w.y, x.y, acc);
        acc = fmaf(w.z, x.z, acc);
        acc = fmaf(w.w, x.w, acc);
    }
    acc += __shfl_down_sync(0xffffffffu, acc, 4, 8);
    acc += __shfl_down_sync(0xffffffffu, acc, 2, 8);
    acc += __shfl_down_sync(0xffffffffu, acc, 1, 8);
    if (lane8 == 0) g_feats[t][k] = acc + b_tag[k];
}

// ---------------- Kernel D: Viterbi decode (one warp) ----------------
__global__ void viterbi_kernel(const float* __restrict__ trans,
                               float* __restrict__ out)
{
    __shared__ float fv[KTAG];
    __shared__ unsigned char bp[TT][KTAG];
    int tid = threadIdx.x;  // 32, thread = next-tag index

    float tr[KTAG];
#pragma unroll
    for (int p = 0; p < KTAG; p++) tr[p] = trans[tid * KTAG + p];
    float stoprow = trans[STOP_TAG * KTAG + tid];

    fv[tid] = (tid == START_TAG) ? 0.f : NEGV;
    __syncwarp();

    for (int t = 0; t < TT; t++) {
        float best = -3.4e38f;
        int bi = 0;
#pragma unroll
        for (int p = 0; p < KTAG; p++) {
            float sc = fv[p] + tr[p];
            if (sc > best) { best = sc; bi = p; }
        }
        bp[t][tid] = (unsigned char)bi;
        float nf = best + g_feats[t][tid];
        __syncwarp();
        fv[tid] = nf;
        __syncwarp();
    }

    float bv = fv[tid] + stoprow;
    int bidx = tid;
#pragma unroll
    for (int off = 16; off > 0; off >>= 1) {
        float ov = __shfl_down_sync(0xffffffffu, bv, off);
        int oi   = __shfl_down_sync(0xffffffffu, bidx, off);
        if (ov > bv || (ov == bv && oi < bidx)) { bv = ov; bidx = oi; }
    }
    bv   = __shfl_sync(0xffffffffu, bv, 0);
    bidx = __shfl_sync(0xffffffffu, bidx, 0);

    if (tid == 0) {
        out[0] = bv;                     // score
        out[TT] = (float)bidx;           // path[T-1] = best
        int tag = bidx;
        for (int t = TT - 1; t >= 1; t--) {
            tag = bp[t][tag];
            out[t] = (float)tag;         // path[t-1]
        }
    }
}

// ---------------- launch ----------------
extern "C" void kernel_launch(void* const* d_in, const int* in_sizes, int n_in,
                              void* d_out, int out_size)
{
    const int*   sentence = (const int*)d_in[0];
    const float* embed    = (const float*)d_in[1];
    const float* w_ih_f   = (const float*)d_in[2];
    const float* w_hh_f   = (const float*)d_in[3];
    const float* b_ih_f   = (const float*)d_in[4];
    const float* b_hh_f   = (const float*)d_in[5];
    const float* w_ih_b   = (const float*)d_in[6];
    const float* w_hh_b   = (const float*)d_in[7];
    const float* b_ih_b   = (const float*)d_in[8];
    const float* b_hh_b   = (const float*)d_in[9];
    const float* h0       = (const float*)d_in[10];
    const float* c0       = (const float*)d_in[11];
    const float* w_tag    = (const float*)d_in[12];
    const float* b_tag    = (const float*)d_in[13];
    const float* trans    = (const float*)d_in[14];
    float* out = (float*)d_out;

    // poison exchange slots: 131072 float4 / 256 = 512 blocks
    poison_kernel<<<512, 256>>>();

    dim3 ggrid(G4 / 128, TT / 128, 2);   // 16 x 4 x 2 = 128 blocks
    gemm_xw_kernel<<<ggrid, 256>>>(sentence, embed,
                                   w_ih_f, b_ih_f, b_hh_f,
                                   w_ih_b, b_ih_b, b_hh_b);

    lstm_kernel<<<2 * NBD, LSTM_THREADS>>>(w_hh_f, w_hh_b, h0, c0);

    tag_kernel<<<TT, 256>>>(w_tag, b_tag);

    viterbi_kernel<<<1, 32>>>(trans, out);
}

// round 8
// speedup vs baseline: 2.2264x; 2.2264x over previous
#include <cuda_runtime.h>
#include <cstdint>

// Problem constants
#define TT   512      // sequence length
#define EE   1024     // embedding dim
#define HDIM 512      // per-direction hidden
#define G4   2048     // 4*HDIM gate rows
#define KTAG 32       // tags
#define NEGV (-10000.0f)
#define START_TAG 30
#define STOP_TAG  31

// LSTM recurrent kernel config
#define NBD  64              // blocks per direction
#define JPB  (HDIM / NBD)    // h-indices per block = 8
#define SENT 0x7FC00001u     // NaN sentinel: finite dot+bias / sig*tanh can never produce it

// ---------------- scratch (device globals; no allocation) ----------------
__device__ float g_xw[2][TT][G4];          // input projections + biases (scan-step indexed, POISONED)
__device__ float g_lstm[TT][2 * HDIM];     // concatenated [hf | hb] (time indexed)
__device__ float g_feats[TT][KTAG];        // tag scores
__device__ float g_hx[2][TT][NBD][JPB];    // per-step h exchange slots (POISONED)

#define XW_F4   524288      // float4 count of g_xw
#define HX_F4   131072      // float4 count of g_hx

// ---------------- asm helpers ----------------
__device__ __forceinline__ float4 ldg_relaxed_v4(const float4* p) {
    float4 v;
    asm volatile("ld.global.relaxed.gpu.v4.f32 {%0,%1,%2,%3}, [%4];"
                 : "=f"(v.x), "=f"(v.y), "=f"(v.z), "=f"(v.w) : "l"(p) : "memory");
    return v;
}
__device__ __forceinline__ float ldg_relaxed_f32(const float* p) {
    float v;
    asm volatile("ld.global.relaxed.gpu.f32 %0, [%1];" : "=f"(v) : "l"(p) : "memory");
    return v;
}
__device__ __forceinline__ void stg_relaxed_f32(float* p, float v) {
    asm volatile("st.global.relaxed.gpu.f32 [%0], %1;" :: "l"(p), "f"(v) : "memory");
}
__device__ __forceinline__ void stg_relaxed_v4(float4* p, float4 v) {
    asm volatile("st.global.relaxed.gpu.v4.f32 [%0], {%1,%2,%3,%4};"
                 :: "l"(p), "f"(v.x), "f"(v.y), "f"(v.z), "f"(v.w) : "memory");
}
__device__ __forceinline__ bool has_sent(float4 v) {
    return (__float_as_uint(v.x) == SENT) | (__float_as_uint(v.y) == SENT) |
           (__float_as_uint(v.z) == SENT) | (__float_as_uint(v.w) == SENT);
}
// packed f32x2 FMA (sm_100+; ptxas never emits this from C++)
__device__ __forceinline__ void fma2(uint64_t& d, uint64_t a, uint64_t b) {
    asm("fma.rn.f32x2 %0, %1, %2, %0;" : "+l"(d) : "l"(a), "l"(b));
}
__device__ __forceinline__ uint64_t pack2(float x, float y) {
    uint64_t r; asm("mov.b64 %0, {%1,%2};" : "=l"(r) : "f"(x), "f"(y)); return r;
}
__device__ __forceinline__ float2 unpack2(uint64_t v) {
    float2 f; asm("mov.b64 {%0,%1}, %2;" : "=f"(f.x), "=f"(f.y) : "l"(v)); return f;
}
__device__ __forceinline__ void lds_v2_u64(uint32_t addr, uint64_t& x, uint64_t& y) {
    asm volatile("ld.shared.v2.b64 {%0,%1}, [%2];" : "=l"(x), "=l"(y) : "r"(addr));
}
// fast activations: MUFU-based, rel err ~1e-6 (safe vs argmax margins)
__device__ __forceinline__ float fast_sig(float x) {
    return __fdividef(1.f, 1.f + __expf(-x));
}
__device__ __forceinline__ float fast_tanh(float x) {
    return 1.f - __fdividef(2.f, __expf(2.f * x) + 1.f);
}

// ---------------- poison g_xw + g_hx each launch ----------------
__global__ __launch_bounds__(256) void poison_kernel() {
    int i = blockIdx.x * 256 + threadIdx.x;   // 2560*256 = 655360 = XW_F4+HX_F4
    float4 v = make_float4(__uint_as_float(SENT), __uint_as_float(SENT),
                           __uint_as_float(SENT), __uint_as_float(SENT));
    if (i < XW_F4)      ((float4*)g_xw)[i] = v;
    else                ((float4*)g_hx)[i - XW_F4] = v;
}

// ---------------- Fused kernel: GEMM blocks + persistent LSTM blocks -----
// Blocks [0,128):  embed-gather + input-projection GEMM, 128x128 tile,
//                  epilogue relaxed-stores into poisoned g_xw.
// Blocks [128,256): persistent LSTM; gate leaders POLL g_xw (data-is-flag),
//                  h exchange via poisoned per-step slots, dependent
//                  (self-throttled) polling.
// __launch_bounds__(256,2): 2 blocks/SM -> all 256 blocks co-resident,
// GEMM overlaps the LSTM's latency-bound recurrence.
__global__ __launch_bounds__(256, 2) void fused_kernel(
    const int* __restrict__ sentence,
    const float* __restrict__ embed,
    const float* __restrict__ w_ih_f, const float* __restrict__ b_ih_f,
    const float* __restrict__ b_hh_f,
    const float* __restrict__ w_ih_b, const float* __restrict__ b_ih_b,
    const float* __restrict__ b_hh_b,
    const float* __restrict__ w_hh_f, const float* __restrict__ w_hh_b,
    const float* __restrict__ h0, const float* __restrict__ c0)
{
    __shared__ __align__(16) float smem_pool[2048];   // 8 KB
    int bid = blockIdx.x;
    int tid = threadIdx.x;

    if (bid < 128) {
        // ================= GEMM role =================
        float* As = smem_pool;            // [8][128]
        float* Bs = smem_pool + 1024;     // [8][128]
        int n0  = (bid & 15) * 128;       // gate-row tile
        int dir = (bid >> 4) & 1;
        int m0  = (bid >> 5) * 128;       // scan-step tile (early steps first)
        const float* W  = dir ? w_ih_b : w_ih_f;
        const float* Bi = dir ? b_ih_b : b_ih_f;
        const float* Bh = dir ? b_hh_b : b_hh_f;

        int tx = tid & 15;                // 8 output cols
        int ty = tid >> 4;                // 8 output rows
        int lrow = tid >> 1;              // load row
        int lq   = tid & 1;               // float4 within 8-wide k slab

        int sglob = m0 + lrow;
        int sidx  = dir ? (TT - 1 - sglob) : sglob;
        const float* aptr = embed + (size_t)sentence[sidx] * EE + lq * 4;
        const float* bptr = W + (size_t)(n0 + lrow) * EE + lq * 4;

        uint64_t acc2[8][4];
#pragma unroll
        for (int i = 0; i < 8; i++)
#pragma unroll
            for (int j = 0; j < 4; j++) acc2[i][j] = 0ull;

        uint32_t bs_base = (uint32_t)__cvta_generic_to_shared(&Bs[tx * 8]);
        uint32_t as_base = (uint32_t)__cvta_generic_to_shared(&As[ty * 8]);

        float4 a_nx = *(const float4*)aptr;
        float4 b_nx = *(const float4*)bptr;

        for (int k0 = 0; k0 < EE; k0 += 8) {
            As[(lq * 4 + 0) * 128 + lrow] = a_nx.x;
            As[(lq * 4 + 1) * 128 + lrow] = a_nx.y;
            As[(lq * 4 + 2) * 128 + lrow] = a_nx.z;
            As[(lq * 4 + 3) * 128 + lrow] = a_nx.w;
            Bs[(lq * 4 + 0) * 128 + lrow] = b_nx.x;
            Bs[(lq * 4 + 1) * 128 + lrow] = b_nx.y;
            Bs[(lq * 4 + 2) * 128 + lrow] = b_nx.z;
            Bs[(lq * 4 + 3) * 128 + lrow] = b_nx.w;
            __syncthreads();

            if (k0 + 8 < EE) {
                a_nx = *(const float4*)(aptr + k0 + 8);
                b_nx = *(const float4*)(bptr + k0 + 8);
            }

#pragma unroll
            for (int k = 0; k < 8; k++) {
                uint64_t a01, a23, a45, a67;
                lds_v2_u64(as_base + k * 512,      a01, a23);
                lds_v2_u64(as_base + k * 512 + 16, a45, a67);
                uint64_t b01, b23, b45, b67;
                lds_v2_u64(bs_base + k * 512,      b01, b23);
                lds_v2_u64(bs_base + k * 512 + 16, b45, b67);
                float2 a0 = unpack2(a01), a1 = unpack2(a23);
                float2 a2 = unpack2(a45), a3 = unpack2(a67);
                float a[8] = {a0.x, a0.y, a1.x, a1.y, a2.x, a2.y, a3.x, a3.y};
#pragma unroll
                for (int i = 0; i < 8; i++) {
                    uint64_t aa = pack2(a[i], a[i]);
                    fma2(acc2[i][0], aa, b01);
                    fma2(acc2[i][1], aa, b23);
                    fma2(acc2[i][2], aa, b45);
                    fma2(acc2[i][3], aa, b67);
                }
            }
            __syncthreads();
        }

        int rbase = n0 + tx * 8;
        float4 bi0 = *(const float4*)(Bi + rbase);
        float4 bi1 = *(const float4*)(Bi + rbase + 4);
        float4 bh0 = *(const float4*)(Bh + rbase);
        float4 bh1 = *(const float4*)(Bh + rbase + 4);
        float bias[8] = {bi0.x + bh0.x, bi0.y + bh0.y, bi0.z + bh0.z, bi0.w + bh0.w,
                         bi1.x + bh1.x, bi1.y + bh1.y, bi1.z + bh1.z, bi1.w + bh1.w};
#pragma unroll
        for (int i = 0; i < 8; i++) {
            int m = m0 + ty * 8 + i;
            float2 p0 = unpack2(acc2[i][0]);
            float2 p1 = unpack2(acc2[i][1]);
            float2 p2 = unpack2(acc2[i][2]);
            float2 p3 = unpack2(acc2[i][3]);
            float4 o0 = make_float4(p0.x + bias[0], p0.y + bias[1],
                                    p1.x + bias[2], p1.y + bias[3]);
            float4 o1 = make_float4(p2.x + bias[4], p2.y + bias[5],
                                    p3.x + bias[6], p3.y + bias[7]);
            stg_relaxed_v4((float4*)&g_xw[dir][m][rbase],     o0);
            stg_relaxed_v4((float4*)&g_xw[dir][m][rbase + 4], o1);
        }
    } else {
        // ================= LSTM role =================
        float* hbuf = smem_pool;          // HDIM floats (2 KB)
        int lbid = bid - 128;
        int dir = lbid / NBD;
        int blk = lbid % NBD;
        int j0  = blk * JPB;
        int wid  = tid >> 5;              // warp = owned j offset (0..7)
        int lane = tid & 31;
        int gate = lane >> 3;             // 0..3 = i,f,g,o
        int k8   = lane & 7;              // 64-element segment index

        const float* w_hh = dir ? w_hh_b : w_hh_f;
        int jglob = j0 + wid;

        // Weights: row (gate*HDIM + jglob), rotated 16B chunks (conflict-free)
        const ulonglong2* wrow =
            (const ulonglong2*)(w_hh + (size_t)(gate * HDIM + jglob) * HDIM);
        uint64_t wp[32];
#pragma unroll
        for (int i = 0; i < 16; i++) {
            int F = k8 * 16 + ((i + k8) & 15);
            ulonglong2 wv = wrow[F];
            wp[2 * i]     = wv.x;
            wp[2 * i + 1] = wv.y;
        }

        float c_reg = (lane == 0) ? c0[dir * HDIM + jglob] : 0.f;

        int pw = tid >> 1;                // writer block this thread tracks (tid<128)
        int pq = tid & 1;                 // which 16B chunk of that writer's payload
        const float* xwrow = &g_xw[dir][0][gate * HDIM + jglob];
        const ulonglong2* h16 = (const ulonglong2*)hbuf;

        for (int s = 0; s < TT; s++) {
            int t = dir ? (TT - 1 - s) : s;

            // xw poll (gate leaders) — data-is-flag vs concurrent GEMM blocks.
            // Dependent loop: self-throttled (~1 sample per L2 latency).
            float xwv = 0.f;
            if (k8 == 0) {
                const float* p = xwrow + (size_t)s * G4;
                do { xwv = ldg_relaxed_f32(p); } while (__float_as_uint(xwv) == SENT);
            }

            // h poll into registers (overlaps straggler warps' step s-1 tail)
            float4 hv4;
            if (s > 0 && tid < 128) {
                const float4* src = (const float4*)&g_hx[dir][s - 1][pw][0] + pq;
                do { hv4 = ldg_relaxed_v4(src); } while (has_sent(hv4));
            }
            __syncthreads();   // bar1: all warps done reading hbuf at step s-1

            if (s == 0) {
                if (tid < 128)
                    ((float4*)hbuf)[tid] = ((const float4*)(h0 + dir * HDIM))[tid];
            } else if (tid < 128) {
                ((float4*)hbuf)[tid] = hv4;
            }
            __syncthreads();   // bar2: hbuf ready

            // dot: 64 elements per lane, rotated -> conflict-free LDS.128
            uint64_t accA = 0ull, accB = 0ull;
#pragma unroll
            for (int i = 0; i < 16; i++) {
                int F = k8 * 16 + ((i + k8) & 15);
                ulonglong2 hp = h16[F];
                fma2(accA, wp[2 * i],     hp.x);
                fma2(accB, wp[2 * i + 1], hp.y);
            }
            float2 fA = unpack2(accA), fB = unpack2(accB);
            float acc = (fA.x + fA.y) + (fB.x + fB.y);
            acc += __shfl_down_sync(0xffffffffu, acc, 4, 8);
            acc += __shfl_down_sync(0xffffffffu, acc, 2, 8);
            acc += __shfl_down_sync(0xffffffffu, acc, 1, 8);

            // gate leaders (lanes 0,8,16,24) activate in parallel
            float red = acc + xwv;
            float act = (gate == 2) ? fast_tanh(red) : fast_sig(red);
            float fS = __shfl_sync(0xffffffffu, act, 8);
            float gS = __shfl_sync(0xffffffffu, act, 16);
            float oS = __shfl_sync(0xffffffffu, act, 24);
            if (lane == 0) {
                c_reg = fmaf(fS, c_reg, act * gS);    // act = sigmoid(i)
                float hv = oS * fast_tanh(c_reg);
                stg_relaxed_f32(&g_hx[dir][s][blk][wid], hv);   // critical path
                g_lstm[t][dir * HDIM + jglob] = hv;             // for tag kernel
            }
        }
    }
}

// ---------------- Kernel C: tag projection ----------------
__global__ __launch_bounds__(256) void tag_kernel(
    const float* __restrict__ w_tag, const float* __restrict__ b_tag)
{
    int t = blockIdx.x;
    __shared__ __align__(16) float row[2 * HDIM];
    int tid = threadIdx.x; // 256
    ((float4*)row)[tid] = ((const float4*)&g_lstm[t][0])[tid];
    __syncthreads();

    int lane8 = tid & 7;
    int k = tid >> 3;     // 0..31
    const float4* wr = (const float4*)(w_tag + (size_t)k * 2 * HDIM);
    const float4* r4 = (const float4*)row;
    float acc = 0.f;
#pragma unroll
    for (int i = 0; i < 32; i++) {
        float4 w = wr[lane8 + 8 * i];
        float4 x = r4[lane8 + 8 * i];
        acc = fmaf(w.x, x.x, acc);
        acc = fmaf(w.y, x.y, acc);
        acc = fmaf(w.z, x.z, acc);
        acc = fmaf(w.w, x.w, acc);
    }
    acc += __shfl_down_sync(0xffffffffu, acc, 4, 8);
    acc += __shfl_down_sync(0xffffffffu, acc, 2, 8);
    acc += __shfl_down_sync(0xffffffffu, acc, 1, 8);
    if (lane8 == 0) g_feats[t][k] = acc + b_tag[k];
}

// ---------------- Kernel D: Viterbi decode (one warp) ----------------
__global__ void viterbi_kernel(const float* __restrict__ trans,
                               float* __restrict__ out)
{
    __shared__ float fv[KTAG];
    __shared__ unsigned char bp[TT][KTAG];
    int tid = threadIdx.x;  // 32, thread = next-tag index

    float tr[KTAG];
#pragma unroll
    for (int p = 0; p < KTAG; p++) tr[p] = trans[tid * KTAG + p];
    float stoprow = trans[STOP_TAG * KTAG + tid];

    fv[tid] = (tid == START_TAG) ? 0.f : NEGV;
    __syncwarp();

    for (int t = 0; t < TT; t++) {
        float best = -3.4e38f;
        int bi = 0;
#pragma unroll
        for (int p = 0; p < KTAG; p++) {
            float sc = fv[p] + tr[p];
            if (sc > best) { best = sc; bi = p; }
        }
        bp[t][tid] = (unsigned char)bi;
        float nf = best + g_feats[t][tid];
        __syncwarp();
        fv[tid] = nf;
        __syncwarp();
    }

    float bv = fv[tid] + stoprow;
    int bidx = tid;
#pragma unroll
    for (int off = 16; off > 0; off >>= 1) {
        float ov = __shfl_down_sync(0xffffffffu, bv, off);
        int oi   = __shfl_down_sync(0xffffffffu, bidx, off);
        if (ov > bv || (ov == bv && oi < bidx)) { bv = ov; bidx = oi; }
    }
    bv   = __shfl_sync(0xffffffffu, bv, 0);
    bidx = __shfl_sync(0xffffffffu, bidx, 0);

    if (tid == 0) {
        out[0] = bv;                     // score
        out[TT] = (float)bidx;           // path[T-1] = best
        int tag = bidx;
        for (int t = TT - 1; t >= 1; t--) {
            tag = bp[t][tag];
            out[t] = (float)tag;         // path[t-1]
        }
    }
}

// ---------------- launch ----------------
extern "C" void kernel_launch(void* const* d_in, const int* in_sizes, int n_in,
                              void* d_out, int out_size)
{
    const int*   sentence = (const int*)d_in[0];
    const float* embed    = (const float*)d_in[1];
    const float* w_ih_f   = (const float*)d_in[2];
    const float* w_hh_f   = (const float*)d_in[3];
    const float* b_ih_f   = (const float*)d_in[4];
    const float* b_hh_f   = (const float*)d_in[5];
    const float* w_ih_b   = (const float*)d_in[6];
    const float* w_hh_b   = (const float*)d_in[7];
    const float* b_ih_b   = (const float*)d_in[8];
    const float* b_hh_b   = (const float*)d_in[9];
    const float* h0       = (const float*)d_in[10];
    const float* c0       = (const float*)d_in[11];
    const float* w_tag    = (const float*)d_in[12];
    const float* b_tag    = (const float*)d_in[13];
    const float* trans    = (const float*)d_in[14];
    float* out = (float*)d_out;

    // poison g_xw + g_hx: 655360 float4 / 256 = 2560 blocks
    poison_kernel<<<2560, 256>>>();

    // fused GEMM (blocks 0-127) + persistent LSTM (blocks 128-255)
    fused_kernel<<<256, 256>>>(sentence, embed,
                               w_ih_f, b_ih_f, b_hh_f,
                               w_ih_b, b_ih_b, b_hh_b,
                               w_hh_f, w_hh_b, h0, c0);

    tag_kernel<<<TT, 256>>>(w_tag, b_tag);

    viterbi_kernel<<<1, 32>>>(trans, out);
}